// round 6
// baseline (speedup 1.0000x reference)
#include <cuda_runtime.h>

#define NN 10000
#define NE 160000
#define NGB 16
#define DD 256
#define HH 4
#define CC 64
#define LL 5
#define NEG 0.2f

// ---------------- scratch (device globals; no allocs allowed) ----------------
__device__ float g_h[NN * DD];
__device__ float g_xh[NN * DD];
__device__ float g_as[NN * HH];
__device__ float g_ad[NN * HH];
__device__ float g_ae[NE * LL * HH];       // per sorted-edge, [edge][l*4+h]
__device__ float g_aeself[NN * LL * HH];   // per node self-loop a_e
__device__ float g_v[LL * HH * DD];        // gat_ew[l] projected by att_edge
__device__ int   g_cnt[NN];
__device__ int   g_rowptr[NN + 1];
__device__ int   g_cursor[NN];
__device__ int   g_src[NE];                // src node per sorted edge
__device__ int   g_eid[NE];                // original edge id per sorted edge
__device__ float g_ghid[NN * DD];
__device__ float g_gate[NN];
__device__ float g_gemb[NGB * DD];

__device__ __forceinline__ float leaky(float x) { return x > 0.f ? x : NEG * x; }

// Buffer selectors — device globals must be resolved in DEVICE code, never
// passed as kernel args from host (host sees the shadow symbol address).
#define BUF_EXT  0
#define BUF_H    1
#define BUF_XH   2
#define BUF_GHID 3
__device__ __forceinline__ const float* sel_cbuf(int s, const float* ext) {
    switch (s) {
        case BUF_H:    return g_h;
        case BUF_XH:   return g_xh;
        case BUF_GHID: return g_ghid;
        default:       return ext;
    }
}
__device__ __forceinline__ float* sel_buf(int s) {
    switch (s) {
        case BUF_XH:   return g_xh;
        case BUF_GHID: return g_ghid;
        default:       return g_h;
    }
}

// ---------------- CSR build ----------------
__global__ void k_zero() {
    int i = blockIdx.x * blockDim.x + threadIdx.x;
    if (i < NN) { g_cnt[i] = 0; g_cursor[i] = 0; }
}

__global__ void k_hist(const int* __restrict__ ei) {
    int e = blockIdx.x * blockDim.x + threadIdx.x;
    if (e < NE) atomicAdd(&g_cnt[ei[NE + e]], 1);
}

__global__ void k_scan() {
    __shared__ int s[1024];
    __shared__ int carry;
    int tid = threadIdx.x;
    if (tid == 0) { carry = 0; g_rowptr[0] = 0; }
    __syncthreads();
    for (int base = 0; base < NN; base += 1024) {
        int i = base + tid;
        int v = (i < NN) ? g_cnt[i] : 0;
        s[tid] = v;
        __syncthreads();
        for (int off = 1; off < 1024; off <<= 1) {
            int t = (tid >= off) ? s[tid - off] : 0;
            __syncthreads();
            s[tid] += t;
            __syncthreads();
        }
        if (i < NN) g_rowptr[i + 1] = carry + s[tid];
        __syncthreads();
        if (tid == 0) carry += s[1023];
        __syncthreads();
    }
}

__global__ void k_scatter(const int* __restrict__ ei) {
    int e = blockIdx.x * blockDim.x + threadIdx.x;
    if (e >= NE) return;
    int d = ei[NE + e];
    int pos = g_rowptr[d] + atomicAdd(&g_cursor[d], 1);
    g_eid[pos] = e;
    g_src[pos] = ei[e];
}

// ---------------- v[l,h,k] = sum_c gat_ew[l][k][h*64+c] * att_edge[l][h][c] ----
__global__ void k_compv(const float* __restrict__ gat_ew, const float* __restrict__ att_edge) {
    int id = blockIdx.x * blockDim.x + threadIdx.x;
    if (id >= LL * HH * DD) return;
    int k = id & (DD - 1);
    int lh = id >> 8;           // l*4+h
    int l = lh >> 2, h = lh & 3;
    float s = 0.f;
    const float* wcol = gat_ew + ((size_t)l * DD + k) * DD + h * CC;
    const float* av = att_edge + (size_t)lh * CC;
    for (int c = 0; c < CC; c++) s += wcol[c] * av[c];
    g_v[lh * DD + k] = s;
}

// ---------------- generic GEMM: C[M,256] = act(A[M,K] @ W[K,256] + bias) ------
#define BM 64
#define BN 64
#define BK 16
__global__ void k_gemm(const float* __restrict__ Aext, const float* __restrict__ W,
                       const float* __restrict__ bias, int aSel, int cSel,
                       int M, int K, int doRelu) {
    const float* A = sel_cbuf(aSel, Aext);
    float* Cmat = sel_buf(cSel);
    __shared__ float As[BK][BM];
    __shared__ float Ws[BK][BN];
    int tid = threadIdx.x;
    int tx = tid & 15, ty = tid >> 4;
    int m0 = blockIdx.x * BM;
    int n0 = blockIdx.y * BN;
    float acc[4][4] = {};
    for (int k0 = 0; k0 < K; k0 += BK) {
#pragma unroll
        for (int i = 0; i < 4; i++) {
            int idx = tid + i * 256;
            int m = idx >> 4, k = idx & 15;
            float v = 0.f;
            if (m0 + m < M && k0 + k < K) v = A[(size_t)(m0 + m) * K + k0 + k];
            As[k][m] = v;
        }
#pragma unroll
        for (int i = 0; i < 4; i++) {
            int idx = tid + i * 256;
            int k = idx >> 6, n = idx & 63;
            float v = 0.f;
            if (k0 + k < K) v = W[(size_t)(k0 + k) * DD + n0 + n];
            Ws[k][n] = v;
        }
        __syncthreads();
#pragma unroll
        for (int k = 0; k < BK; k++) {
            float a[4], w[4];
#pragma unroll
            for (int i = 0; i < 4; i++) a[i] = As[k][ty * 4 + i];
#pragma unroll
            for (int j = 0; j < 4; j++) w[j] = Ws[k][tx * 4 + j];
#pragma unroll
            for (int i = 0; i < 4; i++)
#pragma unroll
                for (int j = 0; j < 4; j++) acc[i][j] += a[i] * w[j];
        }
        __syncthreads();
    }
#pragma unroll
    for (int i = 0; i < 4; i++) {
        int m = m0 + ty * 4 + i;
        if (m >= M) continue;
#pragma unroll
        for (int j = 0; j < 4; j++) {
            int n = n0 + tx * 4 + j;
            float v = acc[i][j] + (bias ? bias[n] : 0.f);
            if (doRelu) v = fmaxf(v, 0.f);
            Cmat[(size_t)m * DD + n] = v;
        }
    }
}

// ---------------- per-sorted-edge: encode edge, project by v → a_e -----------
__global__ void k_ae(const float* __restrict__ ea, const float* __restrict__ eenc_w,
                     const float* __restrict__ eenc_b) {
    int warp = (blockIdx.x * blockDim.x + threadIdx.x) >> 5;
    int lane = threadIdx.x & 31;
    if (warp >= NE) return;
    int e = g_eid[warp];
    float at[12];
#pragma unroll
    for (int k = 0; k < 12; k++) at[k] = ea[e * 12 + k];
    int d0 = lane * 8;
    float er[8];
#pragma unroll
    for (int i = 0; i < 8; i++) er[i] = eenc_b[d0 + i];
#pragma unroll
    for (int k = 0; k < 12; k++)
#pragma unroll
        for (int i = 0; i < 8; i++) er[i] += at[k] * eenc_w[k * DD + d0 + i];
#pragma unroll
    for (int i = 0; i < 8; i++) er[i] = fmaxf(er[i], 0.f);
    float myout = 0.f;
    for (int m = 0; m < LL * HH; m++) {
        float p = 0.f;
#pragma unroll
        for (int i = 0; i < 8; i++) p += er[i] * g_v[m * DD + d0 + i];
#pragma unroll
        for (int o = 16; o; o >>= 1) p += __shfl_xor_sync(0xffffffffu, p, o);
        if (lane == m) myout = p;
    }
    if (lane < LL * HH) g_ae[warp * (LL * HH) + lane] = myout;
}

// ---------------- per-node: mean of incoming edge encodings → a_e(self) ------
__global__ void k_aeself(const float* __restrict__ ea, const float* __restrict__ eenc_w,
                         const float* __restrict__ eenc_b) {
    int warp = (blockIdx.x * blockDim.x + threadIdx.x) >> 5;
    int lane = threadIdx.x & 31;
    if (warp >= NN) return;
    int n = warp;
    int r0 = g_rowptr[n], r1 = g_rowptr[n + 1];
    int d0 = lane * 8;
    float acc[8] = {};
    for (int j = r0; j < r1; j++) {
        int e = g_eid[j];
        float at[12];
#pragma unroll
        for (int k = 0; k < 12; k++) at[k] = ea[e * 12 + k];
        float er[8];
#pragma unroll
        for (int i = 0; i < 8; i++) er[i] = eenc_b[d0 + i];
#pragma unroll
        for (int k = 0; k < 12; k++)
#pragma unroll
            for (int i = 0; i < 8; i++) er[i] += at[k] * eenc_w[k * DD + d0 + i];
#pragma unroll
        for (int i = 0; i < 8; i++) acc[i] += fmaxf(er[i], 0.f);
    }
    float inv = 1.f / fmaxf((float)(r1 - r0), 1.f);
#pragma unroll
    for (int i = 0; i < 8; i++) acc[i] *= inv;
    float myout = 0.f;
    for (int m = 0; m < LL * HH; m++) {
        float p = 0.f;
#pragma unroll
        for (int i = 0; i < 8; i++) p += acc[i] * g_v[m * DD + d0 + i];
#pragma unroll
        for (int o = 16; o; o >>= 1) p += __shfl_xor_sync(0xffffffffu, p, o);
        if (lane == m) myout = p;
    }
    if (lane < LL * HH) g_aeself[n * (LL * HH) + lane] = myout;
}

// ---------------- per-layer: a_s, a_d from xh --------------------------------
__global__ void k_dots(const float* __restrict__ att_src, const float* __restrict__ att_dst,
                       int l) {
    int warp = (blockIdx.x * blockDim.x + threadIdx.x) >> 5;
    int lane = threadIdx.x & 31;
    if (warp >= NN) return;
    int n = warp;
    int myh = lane >> 3;
    int d0 = lane * 8;
    int c0 = (lane & 7) * 8;
    const float* xr = g_xh + (size_t)n * DD + d0;
    const float* as = att_src + ((size_t)l * HH + myh) * CC + c0;
    const float* ad = att_dst + ((size_t)l * HH + myh) * CC + c0;
    float ps = 0.f, pd = 0.f;
#pragma unroll
    for (int i = 0; i < 8; i++) { float xv = xr[i]; ps += xv * as[i]; pd += xv * ad[i]; }
#pragma unroll
    for (int o = 4; o; o >>= 1) {
        ps += __shfl_xor_sync(0xffffffffu, ps, o);
        pd += __shfl_xor_sync(0xffffffffu, pd, o);
    }
    if ((lane & 7) == 0) {
        g_as[n * HH + myh] = ps;
        g_ad[n * HH + myh] = pd;
    }
}

// -------- per-layer: softmax-aggregate + bias + LN + relu + residual ---------
__global__ void k_agg(const float* __restrict__ gat_b, const float* __restrict__ ln_g,
                      const float* __restrict__ ln_b, int l) {
    int warp = (blockIdx.x * blockDim.x + threadIdx.x) >> 5;
    int lane = threadIdx.x & 31;
    if (warp >= NN) return;
    int n = warp;
    int myh = lane >> 3;
    int d0 = lane * 8;
    int r0 = g_rowptr[n], r1 = g_rowptr[n + 1];
    float adn = g_ad[n * HH + myh];
    float aself = leaky(g_as[n * HH + myh] + adn + g_aeself[n * (LL * HH) + l * HH + myh]);
    // pass 1: max
    float m = aself;
    for (int j = r0; j < r1; j++) {
        int s = g_src[j];
        float a = leaky(g_as[s * HH + myh] + adn + g_ae[(size_t)j * (LL * HH) + l * HH + myh]);
        m = fmaxf(m, a);
    }
    // pass 2: accumulate
    float den = __expf(aself - m);
    float acc[8];
    {
        const float4* xn = (const float4*)(g_xh + (size_t)n * DD + d0);
        float4 u = xn[0], u2 = xn[1];
        acc[0] = den * u.x;  acc[1] = den * u.y;  acc[2] = den * u.z;  acc[3] = den * u.w;
        acc[4] = den * u2.x; acc[5] = den * u2.y; acc[6] = den * u2.z; acc[7] = den * u2.w;
    }
    for (int j = r0; j < r1; j++) {
        int s = g_src[j];
        float a = leaky(g_as[s * HH + myh] + adn + g_ae[(size_t)j * (LL * HH) + l * HH + myh]);
        float p = __expf(a - m);
        den += p;
        const float4* xs = (const float4*)(g_xh + (size_t)s * DD + d0);
        float4 u = xs[0], u2 = xs[1];
        acc[0] += p * u.x;  acc[1] += p * u.y;  acc[2] += p * u.z;  acc[3] += p * u.w;
        acc[4] += p * u2.x; acc[5] += p * u2.y; acc[6] += p * u2.z; acc[7] += p * u2.w;
    }
    float invden = 1.f / den;
    float o[8];
    float s1 = 0.f, s2 = 0.f;
#pragma unroll
    for (int i = 0; i < 8; i++) {
        o[i] = acc[i] * invden + gat_b[l * DD + d0 + i];
        s1 += o[i];
        s2 += o[i] * o[i];
    }
#pragma unroll
    for (int off = 16; off; off >>= 1) {
        s1 += __shfl_xor_sync(0xffffffffu, s1, off);
        s2 += __shfl_xor_sync(0xffffffffu, s2, off);
    }
    float mean = s1 * (1.f / DD);
    float var = s2 * (1.f / DD) - mean * mean;
    float rstd = rsqrtf(var + 1e-5f);
#pragma unroll
    for (int i = 0; i < 8; i++) {
        float y = (o[i] - mean) * rstd * ln_g[l * DD + d0 + i] + ln_b[l * DD + d0 + i];
        y = fmaxf(y, 0.f);
        g_h[(size_t)n * DD + d0 + i] += y;
    }
}

// ---------------- gate scalar: gate[n] = ghid[n]·w2 + b2 ---------------------
__global__ void k_gate(const float* __restrict__ w2, const float* __restrict__ b2) {
    int warp = (blockIdx.x * blockDim.x + threadIdx.x) >> 5;
    int lane = threadIdx.x & 31;
    if (warp >= NN) return;
    int n = warp;
    int d0 = lane * 8;
    float p = 0.f;
#pragma unroll
    for (int i = 0; i < 8; i++) p += g_ghid[(size_t)n * DD + d0 + i] * w2[d0 + i];
#pragma unroll
    for (int o = 16; o; o >>= 1) p += __shfl_xor_sync(0xffffffffu, p, o);
    if (lane == 0) g_gate[n] = p + b2[0];
}

// ---------------- attention pooling per graph --------------------------------
__global__ void k_pool(const int* __restrict__ batch) {
    int b = blockIdx.x;
    int tid = threadIdx.x;
    __shared__ int s_start, s_end;
    __shared__ float red[256];
    if (tid == 0) {
        int lo = 0, hi = NN;
        while (lo < hi) { int mid = (lo + hi) >> 1; if (batch[mid] < b) lo = mid + 1; else hi = mid; }
        s_start = lo;
        lo = s_start; hi = NN;
        while (lo < hi) { int mid = (lo + hi) >> 1; if (batch[mid] < b + 1) lo = mid + 1; else hi = mid; }
        s_end = lo;
    }
    __syncthreads();
    int start = s_start, end = s_end;
    float lm = -1e30f;
    for (int n = start + tid; n < end; n += 256) lm = fmaxf(lm, g_gate[n]);
    red[tid] = lm; __syncthreads();
    for (int off = 128; off; off >>= 1) {
        if (tid < off) red[tid] = fmaxf(red[tid], red[tid + off]);
        __syncthreads();
    }
    float gmax = red[0]; __syncthreads();
    float ls = 0.f;
    for (int n = start + tid; n < end; n += 256) ls += __expf(g_gate[n] - gmax);
    red[tid] = ls; __syncthreads();
    for (int off = 128; off; off >>= 1) {
        if (tid < off) red[tid] += red[tid + off];
        __syncthreads();
    }
    float den = red[0]; __syncthreads();
    float inv = (den > 0.f) ? 1.f / den : 0.f;
    float acc = 0.f;
    for (int n = start; n < end; n++) {
        float w = __expf(g_gate[n] - gmax) * inv;
        acc += w * g_h[(size_t)n * DD + tid];
    }
    g_gemb[b * DD + tid] = (end > start) ? acc : 0.f;
}

// ---------------- readout MLP ------------------------------------------------
__global__ void k_readout(const float* __restrict__ w1, const float* __restrict__ b1,
                          const float* __restrict__ w2, const float* __restrict__ b2,
                          float* __restrict__ out) {
    int b = blockIdx.x;
    int tid = threadIdx.x;
    __shared__ float gv[256];
    __shared__ float hid[256];
    gv[tid] = g_gemb[b * DD + tid];
    __syncthreads();
    float a = b1[tid];
    for (int k = 0; k < DD; k++) a += gv[k] * w1[k * DD + tid];
    hid[tid] = fmaxf(a, 0.f);
    __syncthreads();
    float o = b2[tid];
    for (int k = 0; k < DD; k++) o += hid[k] * w2[k * DD + tid];
    out[b * DD + tid] = o;
}

// ---------------- launch -----------------------------------------------------
extern "C" void kernel_launch(void* const* d_in, const int* in_sizes, int n_in,
                              void* d_out, int out_size) {
    // resolve edge_attr / edge_index order by element count
    int i_ea = 1, i_ei = 2;
    if (in_sizes[1] == 2 * NE) { i_ei = 1; i_ea = 2; }
    const float* x         = (const float*)d_in[0];
    const float* edge_attr = (const float*)d_in[i_ea];
    const int*   edge_idx  = (const int*)d_in[i_ei];
    const int*   batch     = (const int*)d_in[3];
    const float* enc_w  = (const float*)d_in[4];
    const float* enc_b  = (const float*)d_in[5];
    const float* eenc_w = (const float*)d_in[6];
    const float* eenc_b = (const float*)d_in[7];
    const float* gat_w   = (const float*)d_in[8];
    const float* att_src = (const float*)d_in[9];
    const float* att_dst = (const float*)d_in[10];
    const float* att_edge= (const float*)d_in[11];
    const float* gat_ew  = (const float*)d_in[12];
    const float* gat_b   = (const float*)d_in[13];
    const float* ln_g    = (const float*)d_in[14];
    const float* ln_b    = (const float*)d_in[15];
    const float* gate_w1 = (const float*)d_in[16];
    const float* gate_b1 = (const float*)d_in[17];
    const float* gate_w2 = (const float*)d_in[18];
    const float* gate_b2 = (const float*)d_in[19];
    const float* ro_w1   = (const float*)d_in[20];
    const float* ro_b1   = (const float*)d_in[21];
    const float* ro_w2   = (const float*)d_in[22];
    const float* ro_b2   = (const float*)d_in[23];
    float* out = (float*)d_out;

    const int T = 256;
    dim3 gemm_grid((NN + BM - 1) / BM, DD / BN);

    // CSR build
    k_zero<<<(NN + T - 1) / T, T>>>();
    k_hist<<<(NE + T - 1) / T, T>>>(edge_idx);
    k_scan<<<1, 1024>>>();
    k_scatter<<<(NE + T - 1) / T, T>>>(edge_idx);

    // edge projections
    k_compv<<<(LL * HH * DD + T - 1) / T, T>>>(gat_ew, att_edge);
    k_ae<<<(NE * 32 + T - 1) / T, T>>>(edge_attr, eenc_w, eenc_b);
    k_aeself<<<(NN * 32 + T - 1) / T, T>>>(edge_attr, eenc_w, eenc_b);

    // node encoder: g_h = relu(x @ enc_w + enc_b)
    k_gemm<<<gemm_grid, T>>>(x, enc_w, enc_b, BUF_EXT, BUF_H, NN, 42, 1);

    // GAT layers
    for (int l = 0; l < LL; l++) {
        k_gemm<<<gemm_grid, T>>>(nullptr, gat_w + (size_t)l * DD * DD, nullptr,
                                 BUF_H, BUF_XH, NN, DD, 0);
        k_dots<<<(NN * 32 + T - 1) / T, T>>>(att_src, att_dst, l);
        k_agg<<<(NN * 32 + T - 1) / T, T>>>(gat_b, ln_g, ln_b, l);
    }

    // pooling gate + readout
    k_gemm<<<gemm_grid, T>>>(nullptr, gate_w1, gate_b1, BUF_H, BUF_GHID, NN, DD, 1);
    k_gate<<<(NN * 32 + T - 1) / T, T>>>(gate_w2, gate_b2);
    k_pool<<<NGB, T>>>(batch);
    k_readout<<<NGB, T>>>(ro_w1, ro_b1, ro_w2, ro_b2, out);
}

// round 10
// speedup vs baseline: 2.6238x; 2.6238x over previous
#include <cuda_runtime.h>

#define NN 10000
#define NE 160000
#define NGB 16
#define DD 256
#define HH 4
#define CC 64
#define LL 5
#define NEG 0.2f

// ---------------- scratch (device globals; no allocs allowed) ----------------
__device__ __align__(16) float g_h[NN * DD];
__device__ __align__(16) float g_xh[NN * DD];
__device__ __align__(16) float g_as[NN * HH];
__device__ __align__(16) float g_ad[NN * HH];
__device__ __align__(16) float g_ae[NE * LL * HH];   // per sorted-edge, [edge][l*4+h]
__device__ __align__(16) float g_v[LL * HH * DD];    // gat_ew[l] proj by att_edge
__device__ __align__(16) float g_ws[LL * DD * HH];   // gat_w[l] proj by att_src
__device__ __align__(16) float g_wd[LL * DD * HH];   // gat_w[l] proj by att_dst
__device__ int   g_cnt[NN];
__device__ int   g_rowptr[NN + 1];
__device__ int   g_cursor[NN];
__device__ int   g_src[NE];                // src node per sorted edge
__device__ int   g_eid[NE];                // original edge id per sorted edge
__device__ __align__(16) float g_ghid[NN * DD];
__device__ float g_gate[NN];
__device__ __align__(16) float g_gemb[NGB * DD];

__device__ __forceinline__ float leaky(float x) { return x > 0.f ? x : NEG * x; }

// Buffer selectors — device globals resolved in DEVICE code only.
#define BUF_EXT  0
#define BUF_H    1
#define BUF_XH   2
#define BUF_GHID 3
__device__ __forceinline__ const float* sel_cbuf(int s, const float* ext) {
    switch (s) {
        case BUF_H:    return g_h;
        case BUF_XH:   return g_xh;
        case BUF_GHID: return g_ghid;
        default:       return ext;
    }
}
__device__ __forceinline__ float* sel_buf(int s) {
    switch (s) {
        case BUF_XH:   return g_xh;
        case BUF_GHID: return g_ghid;
        default:       return g_h;
    }
}

// ---------------- CSR build ----------------
__global__ void k_zero() {
    int i = blockIdx.x * blockDim.x + threadIdx.x;
    if (i < NN) { g_cnt[i] = 0; g_cursor[i] = 0; }
}

__global__ void k_hist(const int* __restrict__ ei) {
    int e = blockIdx.x * blockDim.x + threadIdx.x;
    if (e < NE) atomicAdd(&g_cnt[ei[NE + e]], 1);
}

// warp-shuffle scan, 1024 threads, 10 batches
__global__ void k_scan() {
    __shared__ int wsum[32];
    __shared__ int carry;
    int tid = threadIdx.x;
    int lane = tid & 31, wid = tid >> 5;
    if (tid == 0) { carry = 0; g_rowptr[0] = 0; }
    __syncthreads();
    for (int base = 0; base < NN; base += 1024) {
        int i = base + tid;
        int v = (i < NN) ? g_cnt[i] : 0;
        int sc = v;
#pragma unroll
        for (int off = 1; off < 32; off <<= 1) {
            int t = __shfl_up_sync(0xffffffffu, sc, off);
            if (lane >= off) sc += t;
        }
        if (lane == 31) wsum[wid] = sc;
        __syncthreads();
        int cbase = carry;
        if (wid == 0) {
            int w = wsum[lane];
            int s2 = w;
#pragma unroll
            for (int off = 1; off < 32; off <<= 1) {
                int t = __shfl_up_sync(0xffffffffu, s2, off);
                if (lane >= off) s2 += t;
            }
            wsum[lane] = s2;
        }
        __syncthreads();
        int off2 = cbase + (wid ? wsum[wid - 1] : 0);
        if (i < NN) g_rowptr[i + 1] = off2 + sc;
        if (tid == 0) carry = cbase + wsum[31];
        __syncthreads();
    }
}

__global__ void k_scatter(const int* __restrict__ ei) {
    int e = blockIdx.x * blockDim.x + threadIdx.x;
    if (e >= NE) return;
    int d = ei[NE + e];
    int pos = g_rowptr[d] + atomicAdd(&g_cursor[d], 1);
    g_eid[pos] = e;
    g_src[pos] = ei[e];
}

// ------- tables: g_v (edge proj), g_ws/g_wd (node attn proj) -----------------
__global__ void k_tables(const float* __restrict__ gat_ew, const float* __restrict__ att_edge,
                         const float* __restrict__ gat_w, const float* __restrict__ att_src,
                         const float* __restrict__ att_dst) {
    int id = blockIdx.x * blockDim.x + threadIdx.x;
    if (id >= LL * HH * DD) return;
    int k = id & (DD - 1);
    int lh = id >> 8;           // l*4+h
    int l = lh >> 2, h = lh & 3;
    const float* we = gat_ew + ((size_t)l * DD + k) * DD + h * CC;
    const float* wn = gat_w + ((size_t)l * DD + k) * DD + h * CC;
    const float* ave = att_edge + (size_t)lh * CC;
    const float* avs = att_src + (size_t)lh * CC;
    const float* avd = att_dst + (size_t)lh * CC;
    float se = 0.f, ss = 0.f, sd = 0.f;
    for (int c = 0; c < CC; c++) {
        se += we[c] * ave[c];
        float w = wn[c];
        ss += w * avs[c];
        sd += w * avd[c];
    }
    g_v[lh * DD + k] = se;
    g_ws[((size_t)l * DD + k) * HH + h] = ss;
    g_wd[((size_t)l * DD + k) * HH + h] = sd;
}

// ---------------- GEMM: C[M,256] = act(A[M,K] @ W[K,256] + bias) -------------
// A float4 loads ONLY when K % 4 == 0 (row stride must keep 16B alignment);
// K=42 encoder GEMM uses guarded scalar loads.
#define GBM 128
#define GBN 64
#define GBK 16
__global__ __launch_bounds__(256) void k_gemm2(
        const float* __restrict__ Aext, const float* __restrict__ W,
        const float* __restrict__ bias, int aSel, int cSel,
        int M, int K, int doRelu) {
    const float* A = sel_cbuf(aSel, Aext);
    float* C = sel_buf(cSel);
    __shared__ __align__(16) float As[GBK][132];
    __shared__ __align__(16) float Bs[GBK][GBN];
    int tid = threadIdx.x;
    int tx = tid & 15, ty = tid >> 4;          // compute map: 16x16 threads
    int m0 = blockIdx.x * GBM, n0 = blockIdx.y * GBN;
    int ar = tid >> 2;                          // 0..63 (A rows; +64 for second)
    int ac = (tid & 3) * 4;                     // k within tile
    int bk = tid >> 4;                          // 0..15
    int bn = (tid & 15) * 4;
    bool vecA = ((K & 3) == 0);

    float acc[8][4];
#pragma unroll
    for (int i = 0; i < 8; i++)
#pragma unroll
        for (int j = 0; j < 4; j++) acc[i][j] = 0.f;

    int nsteps = (K + GBK - 1) / GBK;
    float4 pa0, pa1, pb;

#define LOADTILE(S) {                                                          \
        int k0 = (S) * GBK;                                                    \
        pa0 = make_float4(0.f,0.f,0.f,0.f);                                    \
        pa1 = make_float4(0.f,0.f,0.f,0.f);                                    \
        int m_a = m0 + ar;                                                     \
        if (m_a < M) {                                                         \
            if (vecA && k0 + ac + 3 < K)                                       \
                pa0 = *(const float4*)(A + (size_t)m_a*K + k0 + ac);           \
            else {                                                             \
                pa0.x = (k0+ac+0 < K) ? A[(size_t)m_a*K + k0+ac+0] : 0.f;      \
                pa0.y = (k0+ac+1 < K) ? A[(size_t)m_a*K + k0+ac+1] : 0.f;      \
                pa0.z = (k0+ac+2 < K) ? A[(size_t)m_a*K + k0+ac+2] : 0.f;      \
                pa0.w = (k0+ac+3 < K) ? A[(size_t)m_a*K + k0+ac+3] : 0.f;      \
            }                                                                  \
        }                                                                      \
        int m_b = m0 + ar + 64;                                                \
        if (m_b < M) {                                                         \
            if (vecA && k0 + ac + 3 < K)                                       \
                pa1 = *(const float4*)(A + (size_t)m_b*K + k0 + ac);           \
            else {                                                             \
                pa1.x = (k0+ac+0 < K) ? A[(size_t)m_b*K + k0+ac+0] : 0.f;      \
                pa1.y = (k0+ac+1 < K) ? A[(size_t)m_b*K + k0+ac+1] : 0.f;      \
                pa1.z = (k0+ac+2 < K) ? A[(size_t)m_b*K + k0+ac+2] : 0.f;      \
                pa1.w = (k0+ac+3 < K) ? A[(size_t)m_b*K + k0+ac+3] : 0.f;      \
            }                                                                  \
        }                                                                      \
        pb = make_float4(0.f,0.f,0.f,0.f);                                     \
        if (k0 + bk < K) pb = *(const float4*)(W + (size_t)(k0+bk)*DD + n0 + bn); \
    }

    LOADTILE(0)
    for (int s = 0; s < nsteps; s++) {
        As[ac+0][ar] = pa0.x; As[ac+1][ar] = pa0.y;
        As[ac+2][ar] = pa0.z; As[ac+3][ar] = pa0.w;
        As[ac+0][ar+64] = pa1.x; As[ac+1][ar+64] = pa1.y;
        As[ac+2][ar+64] = pa1.z; As[ac+3][ar+64] = pa1.w;
        *(float4*)&Bs[bk][bn] = pb;
        __syncthreads();
        if (s + 1 < nsteps) LOADTILE(s + 1)
#pragma unroll
        for (int k = 0; k < GBK; k++) {
            float4 b4 = *(float4*)&Bs[k][tx*4];
            float4 a0 = *(float4*)&As[k][ty*8];
            float4 a1 = *(float4*)&As[k][ty*8+4];
            float av[8] = {a0.x,a0.y,a0.z,a0.w,a1.x,a1.y,a1.z,a1.w};
            float bv[4] = {b4.x,b4.y,b4.z,b4.w};
#pragma unroll
            for (int i = 0; i < 8; i++)
#pragma unroll
                for (int j = 0; j < 4; j++) acc[i][j] += av[i] * bv[j];
        }
        __syncthreads();
    }
#undef LOADTILE

    float4 bv4 = make_float4(0.f,0.f,0.f,0.f);
    if (bias) bv4 = *(const float4*)(bias + n0 + tx*4);
#pragma unroll
    for (int i = 0; i < 8; i++) {
        int m = m0 + ty*8 + i;
        if (m >= M) continue;
        float4 o;
        o.x = acc[i][0] + bv4.x; o.y = acc[i][1] + bv4.y;
        o.z = acc[i][2] + bv4.z; o.w = acc[i][3] + bv4.w;
        if (doRelu) {
            o.x = fmaxf(o.x, 0.f); o.y = fmaxf(o.y, 0.f);
            o.z = fmaxf(o.z, 0.f); o.w = fmaxf(o.w, 0.f);
        }
        *(float4*)(C + (size_t)m * DD + n0 + tx*4) = o;
    }
}

// ------- a_e: 8 edges per warp, tables amortized, smem-staged attrs ----------
__global__ __launch_bounds__(256) void k_ae2(const float* __restrict__ ea,
                                             const float* __restrict__ eenc_w,
                                             const float* __restrict__ eenc_b) {
    __shared__ float s_at[64][12];
    __shared__ __align__(16) float s_out[8][8][20];
    int tid = threadIdx.x;
    int wid = tid >> 5, lane = tid & 31;
    int base = blockIdx.x * 64;
    for (int t = tid; t < 64 * 12; t += 256) {
        int el = t / 12, k = t - el * 12;
        s_at[el][k] = ea[(size_t)g_eid[base + el] * 12 + k];
    }
    __syncthreads();
    int e0 = wid * 8;
    int d0 = lane * 8;
    float er[8][8];
    {
        float4 b0 = *(const float4*)(eenc_b + d0);
        float4 b1 = *(const float4*)(eenc_b + d0 + 4);
#pragma unroll
        for (int e = 0; e < 8; e++) {
            er[e][0]=b0.x; er[e][1]=b0.y; er[e][2]=b0.z; er[e][3]=b0.w;
            er[e][4]=b1.x; er[e][5]=b1.y; er[e][6]=b1.z; er[e][7]=b1.w;
        }
    }
    for (int k = 0; k < 12; k++) {
        float4 w0 = *(const float4*)(eenc_w + k*DD + d0);
        float4 w1 = *(const float4*)(eenc_w + k*DD + d0 + 4);
        float wv[8] = {w0.x,w0.y,w0.z,w0.w,w1.x,w1.y,w1.z,w1.w};
#pragma unroll
        for (int e = 0; e < 8; e++) {
            float a = s_at[e0 + e][k];
#pragma unroll
            for (int i = 0; i < 8; i++) er[e][i] += a * wv[i];
        }
    }
#pragma unroll
    for (int e = 0; e < 8; e++)
#pragma unroll
        for (int i = 0; i < 8; i++) er[e][i] = fmaxf(er[e][i], 0.f);

    for (int m = 0; m < LL * HH; m++) {
        float4 v0 = *(const float4*)(g_v + (size_t)m*DD + d0);
        float4 v1 = *(const float4*)(g_v + (size_t)m*DD + d0 + 4);
        float vv[8] = {v0.x,v0.y,v0.z,v0.w,v1.x,v1.y,v1.z,v1.w};
        float p[8];
#pragma unroll
        for (int e = 0; e < 8; e++) {
            float s = 0.f;
#pragma unroll
            for (int i = 0; i < 8; i++) s += er[e][i] * vv[i];
            p[e] = s;
        }
#pragma unroll
        for (int off = 16; off; off >>= 1)
#pragma unroll
            for (int e = 0; e < 8; e++)
                p[e] += __shfl_xor_sync(0xffffffffu, p[e], off);
        if (lane == 0) {
#pragma unroll
            for (int e = 0; e < 8; e++) s_out[wid][e][m] = p[e];
        }
    }
    __syncwarp();
    // write 8 edges x 20 floats = 40 float4 per warp (stride 80B, 16B-aligned)
    for (int t = lane; t < 40; t += 32) {
        int e = t / 5, q = t - e * 5;
        *(float4*)(g_ae + (size_t)(base + e0 + e) * 20 + q*4) =
            *(float4*)&s_out[wid][e][q*4];
    }
}

// ---------------- per-layer: a_s, a_d from h via ws/wd tables ----------------
__global__ void k_dots2(int l) {
    int warp = (blockIdx.x * blockDim.x + threadIdx.x) >> 5;
    int lane = threadIdx.x & 31;
    if (warp >= NN) return;
    int n = warp;
    int d0 = lane * 8;
    float4 h0 = *(const float4*)(g_h + (size_t)n*DD + d0);
    float4 h1 = *(const float4*)(g_h + (size_t)n*DD + d0 + 4);
    float hr[8] = {h0.x,h0.y,h0.z,h0.w,h1.x,h1.y,h1.z,h1.w};
    float ps[4] = {0,0,0,0}, pd[4] = {0,0,0,0};
    const float* wsb = g_ws + ((size_t)l * DD + d0) * HH;
    const float* wdb = g_wd + ((size_t)l * DD + d0) * HH;
#pragma unroll
    for (int i = 0; i < 8; i++) {
        float4 w4 = *(const float4*)(wsb + i*HH);
        float4 v4 = *(const float4*)(wdb + i*HH);
        ps[0] += hr[i]*w4.x; ps[1] += hr[i]*w4.y; ps[2] += hr[i]*w4.z; ps[3] += hr[i]*w4.w;
        pd[0] += hr[i]*v4.x; pd[1] += hr[i]*v4.y; pd[2] += hr[i]*v4.z; pd[3] += hr[i]*v4.w;
    }
#pragma unroll
    for (int off = 16; off; off >>= 1) {
#pragma unroll
        for (int h = 0; h < 4; h++) {
            ps[h] += __shfl_xor_sync(0xffffffffu, ps[h], off);
            pd[h] += __shfl_xor_sync(0xffffffffu, pd[h], off);
        }
    }
    if (lane == 0) {
        float4 o1 = {ps[0], ps[1], ps[2], ps[3]};
        float4 o2 = {pd[0], pd[1], pd[2], pd[3]};
        *(float4*)(g_as + n*HH) = o1;
        *(float4*)(g_ad + n*HH) = o2;
    }
}

// ------ single-pass online softmax aggregate + self (mean-ae) + LN + res -----
__global__ void k_agg2(const float* __restrict__ gat_b, const float* __restrict__ ln_g,
                       const float* __restrict__ ln_b, int l) {
    int warp = (blockIdx.x * blockDim.x + threadIdx.x) >> 5;
    int lane = threadIdx.x & 31;
    if (warp >= NN) return;
    int n = warp;
    int myh = lane >> 3;
    int d0 = lane * 8;
    int r0 = g_rowptr[n], r1 = g_rowptr[n + 1];
    float asn = g_as[n*HH + myh];
    float adn = g_ad[n*HH + myh];
    float m = -1e30f, den = 0.f, aesum = 0.f;
    float acc[8] = {0,0,0,0,0,0,0,0};
#pragma unroll 2
    for (int j = r0; j < r1; j++) {
        int s = g_src[j];
        float ae = g_ae[(size_t)j * 20 + l*HH + myh];
        aesum += ae;
        float a = leaky(g_as[s*HH + myh] + adn + ae);
        if (a > m) {
            float r = __expf(m - a);
            den *= r;
#pragma unroll
            for (int i = 0; i < 8; i++) acc[i] *= r;
            m = a;
        }
        float p = __expf(a - m);
        den += p;
        const float4* xs = (const float4*)(g_xh + (size_t)s*DD + d0);
        float4 u = xs[0], u2 = xs[1];
        acc[0] += p*u.x;  acc[1] += p*u.y;  acc[2] += p*u.z;  acc[3] += p*u.w;
        acc[4] += p*u2.x; acc[5] += p*u2.y; acc[6] += p*u2.z; acc[7] += p*u2.w;
    }
    // self loop: a_e(self) = mean of incoming raw a_e
    float invc = 1.f / fmaxf((float)(r1 - r0), 1.f);
    float aself = leaky(asn + adn + aesum * invc);
    if (aself > m) {
        float r = __expf(m - aself);
        den *= r;
#pragma unroll
        for (int i = 0; i < 8; i++) acc[i] *= r;
        m = aself;
    }
    {
        float p = __expf(aself - m);
        den += p;
        const float4* xn = (const float4*)(g_xh + (size_t)n*DD + d0);
        float4 u = xn[0], u2 = xn[1];
        acc[0] += p*u.x;  acc[1] += p*u.y;  acc[2] += p*u.z;  acc[3] += p*u.w;
        acc[4] += p*u2.x; acc[5] += p*u2.y; acc[6] += p*u2.z; acc[7] += p*u2.w;
    }
    float invden = 1.f / den;
    float o[8];
    float s1 = 0.f, s2 = 0.f;
#pragma unroll
    for (int i = 0; i < 8; i++) {
        o[i] = acc[i] * invden + gat_b[l*DD + d0 + i];
        s1 += o[i];
        s2 += o[i] * o[i];
    }
#pragma unroll
    for (int off = 16; off; off >>= 1) {
        s1 += __shfl_xor_sync(0xffffffffu, s1, off);
        s2 += __shfl_xor_sync(0xffffffffu, s2, off);
    }
    float mean = s1 * (1.f / DD);
    float var = s2 * (1.f / DD) - mean * mean;
    float rstd = rsqrtf(var + 1e-5f);
#pragma unroll
    for (int i = 0; i < 8; i++) {
        float y = (o[i] - mean) * rstd * ln_g[l*DD + d0 + i] + ln_b[l*DD + d0 + i];
        y = fmaxf(y, 0.f);
        g_h[(size_t)n*DD + d0 + i] += y;
    }
}

// ---------------- gate scalar: gate[n] = ghid[n]·w2 + b2 ---------------------
__global__ void k_gate(const float* __restrict__ w2, const float* __restrict__ b2) {
    int warp = (blockIdx.x * blockDim.x + threadIdx.x) >> 5;
    int lane = threadIdx.x & 31;
    if (warp >= NN) return;
    int n = warp;
    int d0 = lane * 8;
    float p = 0.f;
#pragma unroll
    for (int i = 0; i < 8; i++) p += g_ghid[(size_t)n*DD + d0 + i] * w2[d0 + i];
#pragma unroll
    for (int o = 16; o; o >>= 1) p += __shfl_xor_sync(0xffffffffu, p, o);
    if (lane == 0) g_gate[n] = p + b2[0];
}

// ---------------- attention pooling per graph --------------------------------
__global__ void k_pool(const int* __restrict__ batch) {
    int b = blockIdx.x;
    int tid = threadIdx.x;
    __shared__ int s_start, s_end;
    __shared__ float red[256];
    if (tid == 0) {
        int lo = 0, hi = NN;
        while (lo < hi) { int mid = (lo + hi) >> 1; if (batch[mid] < b) lo = mid + 1; else hi = mid; }
        s_start = lo;
        lo = s_start; hi = NN;
        while (lo < hi) { int mid = (lo + hi) >> 1; if (batch[mid] < b + 1) lo = mid + 1; else hi = mid; }
        s_end = lo;
    }
    __syncthreads();
    int start = s_start, end = s_end;
    float lm = -1e30f;
    for (int n = start + tid; n < end; n += 256) lm = fmaxf(lm, g_gate[n]);
    red[tid] = lm; __syncthreads();
    for (int off = 128; off; off >>= 1) {
        if (tid < off) red[tid] = fmaxf(red[tid], red[tid + off]);
        __syncthreads();
    }
    float gmax = red[0]; __syncthreads();
    float ls = 0.f;
    for (int n = start + tid; n < end; n += 256) ls += __expf(g_gate[n] - gmax);
    red[tid] = ls; __syncthreads();
    for (int off = 128; off; off >>= 1) {
        if (tid < off) red[tid] += red[tid + off];
        __syncthreads();
    }
    float den = red[0]; __syncthreads();
    float inv = (den > 0.f) ? 1.f / den : 0.f;
    float acc = 0.f;
    for (int n = start; n < end; n++) {
        float w = __expf(g_gate[n] - gmax) * inv;
        acc += w * g_h[(size_t)n*DD + tid];
    }
    g_gemb[b*DD + tid] = (end > start) ? acc : 0.f;
}

// ---------------- readout MLP ------------------------------------------------
__global__ void k_readout(const float* __restrict__ w1, const float* __restrict__ b1,
                          const float* __restrict__ w2, const float* __restrict__ b2,
                          float* __restrict__ out) {
    int b = blockIdx.x;
    int tid = threadIdx.x;
    __shared__ float gv[256];
    __shared__ float hid[256];
    gv[tid] = g_gemb[b*DD + tid];
    __syncthreads();
    float a = b1[tid];
    for (int k = 0; k < DD; k++) a += gv[k] * w1[k*DD + tid];
    hid[tid] = fmaxf(a, 0.f);
    __syncthreads();
    float o = b2[tid];
    for (int k = 0; k < DD; k++) o += hid[k] * w2[k*DD + tid];
    out[b*DD + tid] = o;
}

// ---------------- launch -----------------------------------------------------
extern "C" void kernel_launch(void* const* d_in, const int* in_sizes, int n_in,
                              void* d_out, int out_size) {
    int i_ea = 1, i_ei = 2;
    if (in_sizes[1] == 2 * NE) { i_ei = 1; i_ea = 2; }
    const float* x         = (const float*)d_in[0];
    const float* edge_attr = (const float*)d_in[i_ea];
    const int*   edge_idx  = (const int*)d_in[i_ei];
    const int*   batch     = (const int*)d_in[3];
    const float* enc_w  = (const float*)d_in[4];
    const float* enc_b  = (const float*)d_in[5];
    const float* eenc_w = (const float*)d_in[6];
    const float* eenc_b = (const float*)d_in[7];
    const float* gat_w   = (const float*)d_in[8];
    const float* att_src = (const float*)d_in[9];
    const float* att_dst = (const float*)d_in[10];
    const float* att_edge= (const float*)d_in[11];
    const float* gat_ew  = (const float*)d_in[12];
    const float* gat_b   = (const float*)d_in[13];
    const float* ln_g    = (const float*)d_in[14];
    const float* ln_b    = (const float*)d_in[15];
    const float* gate_w1 = (const float*)d_in[16];
    const float* gate_b1 = (const float*)d_in[17];
    const float* gate_w2 = (const float*)d_in[18];
    const float* gate_b2 = (const float*)d_in[19];
    const float* ro_w1   = (const float*)d_in[20];
    const float* ro_b1   = (const float*)d_in[21];
    const float* ro_w2   = (const float*)d_in[22];
    const float* ro_b2   = (const float*)d_in[23];
    float* out = (float*)d_out;

    const int T = 256;
    dim3 ggrid((NN + GBM - 1) / GBM, DD / GBN);

    // CSR build
    k_zero<<<(NN + T - 1) / T, T>>>();
    k_hist<<<(NE + T - 1) / T, T>>>(edge_idx);
    k_scan<<<1, 1024>>>();
    k_scatter<<<(NE + T - 1) / T, T>>>(edge_idx);

    // projection tables + edge attention logits
    k_tables<<<(LL * HH * DD + T - 1) / T, T>>>(gat_ew, att_edge, gat_w, att_src, att_dst);
    k_ae2<<<NE / 64, T>>>(edge_attr, eenc_w, eenc_b);

    // node encoder: g_h = relu(x @ enc_w + enc_b)
    k_gemm2<<<ggrid, T>>>(x, enc_w, enc_b, BUF_EXT, BUF_H, NN, 42, 1);

    // GAT layers
    for (int l = 0; l < LL; l++) {
        k_dots2<<<(NN * 32 + T - 1) / T, T>>>(l);
        k_gemm2<<<ggrid, T>>>(nullptr, gat_w + (size_t)l * DD * DD, nullptr,
                              BUF_H, BUF_XH, NN, DD, 0);
        k_agg2<<<(NN * 32 + T - 1) / T, T>>>(gat_b, ln_g, ln_b, l);
    }

    // pooling gate + readout
    k_gemm2<<<ggrid, T>>>(nullptr, gate_w1, gate_b1, BUF_H, BUF_GHID, NN, DD, 1);
    k_gate<<<(NN * 32 + T - 1) / T, T>>>(gate_w2, gate_b2);
    k_pool<<<NGB, T>>>(batch);
    k_readout<<<NGB, T>>>(ro_w1, ro_b1, ro_w2, ro_b2, out);
}